// round 15
// baseline (speedup 1.0000x reference)
#include <cuda_runtime.h>
#include <cuda_bf16.h>
#include <math.h>
#include <stdint.h>

#define BB 8
#define HH 1024
#define DD 4
#define NTB 32                    // 32x32 tiles per dim in symw
#define NPAIR (NTB*(NTB+1)/2)     // 528 tile-pairs

// Scratch (__device__ globals: allocation-guard safe)
__device__ __align__(16) float    g_sth[BB * HH * DD]; // sin(theta)
__device__ __align__(16) float    g_cth[BB * HH * DD]; // cos(theta)
__device__ __align__(16) uint32_t g_W[(size_t)BB * HH * HH]; // bf16x2: lo=w1, hi=w2

typedef unsigned long long u64;

__device__ __forceinline__ u64 pack2(float x, float y) {
    u64 r; asm("mov.b64 %0, {%1, %2};" : "=l"(r) : "f"(x), "f"(y)); return r;
}
__device__ __forceinline__ u64 ffma2(u64 a, u64 b, u64 c) {
    u64 d; asm("fma.rn.f32x2 %0, %1, %2, %3;" : "=l"(d) : "l"(a), "l"(b), "l"(c)); return d;
}
__device__ __forceinline__ float2 unpk2(u64 v) {
    float x, y; asm("mov.b64 {%0, %1}, %2;" : "=f"(x), "=f"(y) : "l"(v));
    return make_float2(x, y);
}
// pack (hi, lo) fp32 -> bf16x2
__device__ __forceinline__ uint32_t cvt_bf16x2(float hi, float lo) {
    uint32_t r;
    asm("cvt.rn.bf16x2.f32 %0, %1, %2;" : "=r"(r) : "f"(hi), "f"(lo));
    return r;
}

// ---------------------------------------------------------------------------
// Kernel 1: W precompute, fused alpha trig AND theta trig. UNCHANGED from R14
// (measured at DRAM roofline: ~5.7 TB/s effective).
// ---------------------------------------------------------------------------
__global__ __launch_bounds__(256)
void vk_symw_kernel(const float* __restrict__ A,
                    const float* __restrict__ alpha,
                    const float* __restrict__ theta) {
    __shared__ float tA0[32][33], tB0[32][33];  // batch b   (stride 33: conflict-free)
    __shared__ float tA1[32][33], tB1[32][33];  // batch b+1

    const int tid = threadIdx.x;

    // fused theta trig: first 128 blocks, 1 element per thread
    if (blockIdx.x < (BB * HH * DD) / 256) {
        int idx = blockIdx.x * 256 + tid;
        float s, c;
        sincosf(theta[idx], &s, &c);
        g_sth[idx] = s;
        g_cth[idx] = c;
    }

    // triangular decode of blockIdx.x -> (ti, tj)
    int p = blockIdx.x;
    int ti = 0;
    while (p >= NTB - ti) { p -= NTB - ti; ti++; }
    const int tj = ti + p;
    const int i0 = ti * 32, j0 = tj * 32;

    const int r = tid >> 3;
    const int c = (tid & 7) * 4;

    // batch-invariant alpha trig (0.5 folded), computed once, kept in regs
    float2 csij[4], csji[4];
    {
        float4 a4 = *(const float4*)(alpha + (size_t)(i0 + r) * HH + j0 + c);
        float av[4] = {a4.x, a4.y, a4.z, a4.w};
        #pragma unroll
        for (int k = 0; k < 4; k++) {
            float s, cc;
            sincosf(av[k], &s, &cc);
            csij[k] = make_float2(0.5f * cc, 0.5f * s);
        }
    }
    {
        float4 a4 = *(const float4*)(alpha + (size_t)(j0 + r) * HH + i0 + c);
        float av[4] = {a4.x, a4.y, a4.z, a4.w};
        #pragma unroll
        for (int k = 0; k < 4; k++) {
            float s, cc;
            sincosf(av[k], &s, &cc);
            csji[k] = make_float2(0.5f * cc, 0.5f * s);
        }
    }

    for (int b = 0; b < BB; b += 2) {
        const float* Ab0 = A + (size_t)b * HH * HH;
        const float* Ab1 = Ab0 + (size_t)HH * HH;
        // 4 independent loads in flight
        float4 va0 = *(const float4*)(Ab0 + (size_t)(i0 + r) * HH + j0 + c);
        float4 vb0 = *(const float4*)(Ab0 + (size_t)(j0 + r) * HH + i0 + c);
        float4 va1 = *(const float4*)(Ab1 + (size_t)(i0 + r) * HH + j0 + c);
        float4 vb1 = *(const float4*)(Ab1 + (size_t)(j0 + r) * HH + i0 + c);
        __syncthreads();                    // previous pair's reads done
        tA0[r][c + 0] = va0.x; tA0[r][c + 1] = va0.y;
        tA0[r][c + 2] = va0.z; tA0[r][c + 3] = va0.w;
        tB0[r][c + 0] = vb0.x; tB0[r][c + 1] = vb0.y;
        tB0[r][c + 2] = vb0.z; tB0[r][c + 3] = vb0.w;
        tA1[r][c + 0] = va1.x; tA1[r][c + 1] = va1.y;
        tA1[r][c + 2] = va1.z; tA1[r][c + 3] = va1.w;
        tB1[r][c + 0] = vb1.x; tB1[r][c + 1] = vb1.y;
        tB1[r][c + 2] = vb1.z; tB1[r][c + 3] = vb1.w;
        __syncthreads();

        uint32_t oij0[4], oji0[4], oij1[4], oji1[4];
        #pragma unroll
        for (int k = 0; k < 4; k++) {
            // a_lat*2 (0.5 folded into cs): relu(A_ij + A_ji)
            float a10 = fmaxf(tA0[r][c + k] + tB0[c + k][r], 0.f);
            oij0[k] = cvt_bf16x2(a10 * csij[k].y, a10 * csij[k].x); // hi=w2, lo=w1
            float a20 = fmaxf(tB0[r][c + k] + tA0[c + k][r], 0.f);
            oji0[k] = cvt_bf16x2(a20 * csji[k].y, a20 * csji[k].x);
            float a11 = fmaxf(tA1[r][c + k] + tB1[c + k][r], 0.f);
            oij1[k] = cvt_bf16x2(a11 * csij[k].y, a11 * csij[k].x);
            float a21 = fmaxf(tB1[r][c + k] + tA1[c + k][r], 0.f);
            oji1[k] = cvt_bf16x2(a21 * csji[k].y, a21 * csji[k].x);
        }
        *(uint4*)(g_W + ((size_t)b * HH + i0 + r) * HH + j0 + c) =
            make_uint4(oij0[0], oij0[1], oij0[2], oij0[3]);
        *(uint4*)(g_W + ((size_t)(b + 1) * HH + i0 + r) * HH + j0 + c) =
            make_uint4(oij1[0], oij1[1], oij1[2], oij1[3]);
        if (ti != tj) {
            *(uint4*)(g_W + ((size_t)b * HH + j0 + r) * HH + i0 + c) =
                make_uint4(oji0[0], oji0[1], oji0[2], oji0[3]);
            *(uint4*)(g_W + ((size_t)(b + 1) * HH + j0 + r) * HH + i0 + c) =
                make_uint4(oji1[0], oji1[1], oji1[2], oji1[3]);
        }
    }
}

// ---------------------------------------------------------------------------
// Kernel 2: row-streaming accumulation, occupancy-tuned. Block 256 thr = 8
// warps, warp owns 2 rows, block covers 16 rows. Grid (64, 8). acc = 16 regs,
// prefetch = 8 regs -> ~64 regs total -> 4 CTAs/SM = 32 warps resident.
// ---------------------------------------------------------------------------
__global__ __launch_bounds__(256)
void vk_main_kernel(const float* __restrict__ theta,
                    const float* __restrict__ gamma,
                    const float* __restrict__ omega,
                    const float* __restrict__ kappa,
                    float* __restrict__ out) {
    __shared__ ulonglong2 shS[HH];   // sin(theta[b,j,0..3]) as 2x f32x2
    __shared__ ulonglong2 shC[HH];

    const int b   = blockIdx.y;
    const int i0  = blockIdx.x * 16;
    const int tid = threadIdx.x;
    const int warp = tid >> 5;
    const int lane = tid & 31;

    const ulonglong2* sv = (const ulonglong2*)(g_sth + (size_t)b * HH * DD);
    const ulonglong2* cv = (const ulonglong2*)(g_cth + (size_t)b * HH * DD);
    #pragma unroll
    for (int p = 0; p < 4; p++) {
        shS[p * 256 + tid] = sv[p * 256 + tid];
        shC[p * 256 + tid] = cv[p * 256 + tid];
    }
    __syncthreads();

    const int ib = i0 + warp * 2;                       // first of 2 rows
    const uint32_t* Wb = g_W + ((size_t)b * HH + ib) * HH;

    u64 acc[2][4];                                       // [row][s1d01,s1d23,s2d01,s2d23]
    #pragma unroll
    for (int r = 0; r < 2; r++)
        #pragma unroll
        for (int q = 0; q < 4; q++) acc[r][q] = 0;

    // prefetch jq=0
    uint4 nw[2];
    #pragma unroll
    for (int r = 0; r < 2; r++)
        nw[r] = *(const uint4*)(Wb + r * HH + lane * 4);

    for (int jq = 0; jq < 8; jq++) {
        const int jb = jq * 128 + lane * 4;
        uint4 w[2];
        w[0] = nw[0]; w[1] = nw[1];
        if (jq < 7) {
            const int jb2 = jb + 128;
            nw[0] = *(const uint4*)(Wb + 0 * HH + jb2);
            nw[1] = *(const uint4*)(Wb + 1 * HH + jb2);
        }

        #pragma unroll
        for (int k = 0; k < 4; k++) {
            ulonglong2 Sv = shS[jb + k];
            ulonglong2 Cv = shC[jb + k];
            #pragma unroll
            for (int r = 0; r < 2; r++) {
                uint32_t u = (k == 0) ? w[r].x : (k == 1) ? w[r].y
                           : (k == 2) ? w[r].z : w[r].w;
                float w1f = __uint_as_float(u << 16);
                float w2f = __uint_as_float(u & 0xFFFF0000u);
                u64 w1p = pack2(w1f, w1f);
                u64 w2p = pack2(w2f, w2f);
                u64 n2p = pack2(-w2f, -w2f);
                acc[r][0] = ffma2(w1p, Sv.x, acc[r][0]);
                acc[r][0] = ffma2(n2p, Cv.x, acc[r][0]);
                acc[r][1] = ffma2(w1p, Sv.y, acc[r][1]);
                acc[r][1] = ffma2(n2p, Cv.y, acc[r][1]);
                acc[r][2] = ffma2(w1p, Cv.x, acc[r][2]);
                acc[r][2] = ffma2(w2p, Sv.x, acc[r][2]);
                acc[r][3] = ffma2(w1p, Cv.y, acc[r][3]);
                acc[r][3] = ffma2(w2p, Sv.y, acc[r][3]);
            }
        }
    }

    // unpack 8 u64 -> 16 floats, butterfly-reduce across the warp
    float v[16];
    #pragma unroll
    for (int r = 0; r < 2; r++) {
        float2 t2;
        t2 = unpk2(acc[r][0]); v[r * 8 + 0] = t2.x; v[r * 8 + 1] = t2.y;  // s1 d0,d1
        t2 = unpk2(acc[r][1]); v[r * 8 + 2] = t2.x; v[r * 8 + 3] = t2.y;  // s1 d2,d3
        t2 = unpk2(acc[r][2]); v[r * 8 + 4] = t2.x; v[r * 8 + 5] = t2.y;  // s2 d0,d1
        t2 = unpk2(acc[r][3]); v[r * 8 + 6] = t2.x; v[r * 8 + 7] = t2.y;  // s2 d2,d3
    }
    #pragma unroll
    for (int off = 16; off > 0; off >>= 1) {
        #pragma unroll
        for (int q = 0; q < 16; q++)
            v[q] += __shfl_xor_sync(0xFFFFFFFFu, v[q], off);
    }

    if (lane < 2) {
        const int i = ib + lane;
        const float* vv = v + lane * 8;       // [s1_d0..d3, s2_d0..d3]
        const float invH = 1.0f / (float)HH;  // K_COUP=1, DT=1, 0.5 folded
        const size_t base = ((size_t)b * HH + i) * DD;
        float4 si4 = *(const float4*)(g_sth + base);
        float4 ci4 = *(const float4*)(g_cth + base);
        float4 tp4 = *(const float4*)(theta + base);
        float4 om4 = *(const float4*)(omega + (size_t)i * DD);
        float4 kp4 = *(const float4*)(kappa + (size_t)i * DD);
        float g = gamma[(size_t)b * HH + i];

        float4 rr;
        rr.x = tp4.x + om4.x + invH * (ci4.x * vv[0] - si4.x * vv[4]) + kp4.x * (g - tp4.x);
        rr.y = tp4.y + om4.y + invH * (ci4.y * vv[1] - si4.y * vv[5]) + kp4.y * (g - tp4.y);
        rr.z = tp4.z + om4.z + invH * (ci4.z * vv[2] - si4.z * vv[6]) + kp4.z * (g - tp4.z);
        rr.w = tp4.w + om4.w + invH * (ci4.w * vv[3] - si4.w * vv[7]) + kp4.w * (g - tp4.w);
        *(float4*)(out + base) = rr;
    }
}

extern "C" void kernel_launch(void* const* d_in, const int* in_sizes, int n_in,
                              void* d_out, int out_size) {
    const float* theta = (const float*)d_in[0];  // [B,H,D]
    const float* gamma = (const float*)d_in[1];  // [B,H]
    const float* A     = (const float*)d_in[2];  // [B,H,H]
    const float* omega = (const float*)d_in[3];  // [H,D]
    const float* kappa = (const float*)d_in[4];  // [H,D]
    const float* alpha = (const float*)d_in[5];  // [H,H]
    float* out = (float*)d_out;

    vk_symw_kernel<<<NPAIR, 256>>>(A, alpha, theta);
    {
        dim3 grid(HH / 16, BB);
        vk_main_kernel<<<grid, 256>>>(theta, gamma, omega, kappa, out);
    }
}

// round 16
// speedup vs baseline: 1.3790x; 1.3790x over previous
#include <cuda_runtime.h>
#include <cuda_bf16.h>
#include <math.h>
#include <stdint.h>

#define BB 8
#define HH 1024
#define DD 4
#define NTB 32                    // 32x32 tiles per dim in symw
#define NPAIR (NTB*(NTB+1)/2)     // 528 tile-pairs

// Scratch (__device__ globals: allocation-guard safe)
__device__ __align__(16) float    g_sth[BB * HH * DD]; // sin(theta)
__device__ __align__(16) float    g_cth[BB * HH * DD]; // cos(theta)
__device__ __align__(16) uint32_t g_W[(size_t)BB * HH * HH]; // bf16x2: lo=w1, hi=w2

typedef unsigned long long u64;

__device__ __forceinline__ u64 pack2(float x, float y) {
    u64 r; asm("mov.b64 %0, {%1, %2};" : "=l"(r) : "f"(x), "f"(y)); return r;
}
__device__ __forceinline__ u64 ffma2(u64 a, u64 b, u64 c) {
    u64 d; asm("fma.rn.f32x2 %0, %1, %2, %3;" : "=l"(d) : "l"(a), "l"(b), "l"(c)); return d;
}
__device__ __forceinline__ float2 unpk2(u64 v) {
    float x, y; asm("mov.b64 {%0, %1}, %2;" : "=f"(x), "=f"(y) : "l"(v));
    return make_float2(x, y);
}
// pack (hi, lo) fp32 -> bf16x2
__device__ __forceinline__ uint32_t cvt_bf16x2(float hi, float lo) {
    uint32_t r;
    asm("cvt.rn.bf16x2.f32 %0, %1, %2;" : "=r"(r) : "f"(hi), "f"(lo));
    return r;
}

// ---------------------------------------------------------------------------
// Kernel 1: W precompute, fused alpha trig AND theta trig. UNCHANGED
// (measured at DRAM roofline: ~5.7 TB/s effective).
// ---------------------------------------------------------------------------
__global__ __launch_bounds__(256)
void vk_symw_kernel(const float* __restrict__ A,
                    const float* __restrict__ alpha,
                    const float* __restrict__ theta) {
    __shared__ float tA0[32][33], tB0[32][33];  // batch b   (stride 33: conflict-free)
    __shared__ float tA1[32][33], tB1[32][33];  // batch b+1

    const int tid = threadIdx.x;

    // fused theta trig: first 128 blocks, 1 element per thread
    if (blockIdx.x < (BB * HH * DD) / 256) {
        int idx = blockIdx.x * 256 + tid;
        float s, c;
        sincosf(theta[idx], &s, &c);
        g_sth[idx] = s;
        g_cth[idx] = c;
    }

    // triangular decode of blockIdx.x -> (ti, tj)
    int p = blockIdx.x;
    int ti = 0;
    while (p >= NTB - ti) { p -= NTB - ti; ti++; }
    const int tj = ti + p;
    const int i0 = ti * 32, j0 = tj * 32;

    const int r = tid >> 3;
    const int c = (tid & 7) * 4;

    // batch-invariant alpha trig (0.5 folded), computed once, kept in regs
    float2 csij[4], csji[4];
    {
        float4 a4 = *(const float4*)(alpha + (size_t)(i0 + r) * HH + j0 + c);
        float av[4] = {a4.x, a4.y, a4.z, a4.w};
        #pragma unroll
        for (int k = 0; k < 4; k++) {
            float s, cc;
            sincosf(av[k], &s, &cc);
            csij[k] = make_float2(0.5f * cc, 0.5f * s);
        }
    }
    {
        float4 a4 = *(const float4*)(alpha + (size_t)(j0 + r) * HH + i0 + c);
        float av[4] = {a4.x, a4.y, a4.z, a4.w};
        #pragma unroll
        for (int k = 0; k < 4; k++) {
            float s, cc;
            sincosf(av[k], &s, &cc);
            csji[k] = make_float2(0.5f * cc, 0.5f * s);
        }
    }

    for (int b = 0; b < BB; b += 2) {
        const float* Ab0 = A + (size_t)b * HH * HH;
        const float* Ab1 = Ab0 + (size_t)HH * HH;
        // 4 independent loads in flight
        float4 va0 = *(const float4*)(Ab0 + (size_t)(i0 + r) * HH + j0 + c);
        float4 vb0 = *(const float4*)(Ab0 + (size_t)(j0 + r) * HH + i0 + c);
        float4 va1 = *(const float4*)(Ab1 + (size_t)(i0 + r) * HH + j0 + c);
        float4 vb1 = *(const float4*)(Ab1 + (size_t)(j0 + r) * HH + i0 + c);
        __syncthreads();                    // previous pair's reads done
        tA0[r][c + 0] = va0.x; tA0[r][c + 1] = va0.y;
        tA0[r][c + 2] = va0.z; tA0[r][c + 3] = va0.w;
        tB0[r][c + 0] = vb0.x; tB0[r][c + 1] = vb0.y;
        tB0[r][c + 2] = vb0.z; tB0[r][c + 3] = vb0.w;
        tA1[r][c + 0] = va1.x; tA1[r][c + 1] = va1.y;
        tA1[r][c + 2] = va1.z; tA1[r][c + 3] = va1.w;
        tB1[r][c + 0] = vb1.x; tB1[r][c + 1] = vb1.y;
        tB1[r][c + 2] = vb1.z; tB1[r][c + 3] = vb1.w;
        __syncthreads();

        uint32_t oij0[4], oji0[4], oij1[4], oji1[4];
        #pragma unroll
        for (int k = 0; k < 4; k++) {
            // a_lat*2 (0.5 folded into cs): relu(A_ij + A_ji)
            float a10 = fmaxf(tA0[r][c + k] + tB0[c + k][r], 0.f);
            oij0[k] = cvt_bf16x2(a10 * csij[k].y, a10 * csij[k].x); // hi=w2, lo=w1
            float a20 = fmaxf(tB0[r][c + k] + tA0[c + k][r], 0.f);
            oji0[k] = cvt_bf16x2(a20 * csji[k].y, a20 * csji[k].x);
            float a11 = fmaxf(tA1[r][c + k] + tB1[c + k][r], 0.f);
            oij1[k] = cvt_bf16x2(a11 * csij[k].y, a11 * csij[k].x);
            float a21 = fmaxf(tB1[r][c + k] + tA1[c + k][r], 0.f);
            oji1[k] = cvt_bf16x2(a21 * csji[k].y, a21 * csji[k].x);
        }
        *(uint4*)(g_W + ((size_t)b * HH + i0 + r) * HH + j0 + c) =
            make_uint4(oij0[0], oij0[1], oij0[2], oij0[3]);
        *(uint4*)(g_W + ((size_t)(b + 1) * HH + i0 + r) * HH + j0 + c) =
            make_uint4(oij1[0], oij1[1], oij1[2], oij1[3]);
        if (ti != tj) {
            *(uint4*)(g_W + ((size_t)b * HH + j0 + r) * HH + i0 + c) =
                make_uint4(oji0[0], oji0[1], oji0[2], oji0[3]);
            *(uint4*)(g_W + ((size_t)(b + 1) * HH + j0 + r) * HH + i0 + c) =
                make_uint4(oji1[0], oji1[1], oji1[2], oji1[3]);
        }
    }
}

// ---------------------------------------------------------------------------
// Kernel 2: row-streaming accumulation, CONFLICT-FREE trig layout.
// SMEM trig is stored k-major within each 128-j chunk: physical slot
// (chunk*128 + k*32 + lane) holds logical j = chunk*128 + lane*4 + k.
// Compute reads shS[jq*128 + k*32 + lane]: 16B/lane consecutive -> zero
// bank conflicts (vs 16-way conflict of the naive layout).
// Block 256 thr = 8 warps, warp owns 2 rows, block covers 16 rows.
// ---------------------------------------------------------------------------
__global__ __launch_bounds__(256)
void vk_main_kernel(const float* __restrict__ theta,
                    const float* __restrict__ gamma,
                    const float* __restrict__ omega,
                    const float* __restrict__ kappa,
                    float* __restrict__ out) {
    __shared__ ulonglong2 shS[HH];   // permuted sin(theta) (see header comment)
    __shared__ ulonglong2 shC[HH];   // permuted cos(theta)

    const int b   = blockIdx.y;
    const int i0  = blockIdx.x * 16;
    const int tid = threadIdx.x;
    const int warp = tid >> 5;
    const int lane = tid & 31;

    const ulonglong2* sv = (const ulonglong2*)(g_sth + (size_t)b * HH * DD);
    const ulonglong2* cv = (const ulonglong2*)(g_cth + (size_t)b * HH * DD);
    // permuted staging: physical p holds logical j = chunk*128 + (p%32)*4 + (p/32)%4
    #pragma unroll
    for (int it = 0; it < 4; it++) {
        int p = it * 256 + tid;
        int lg = (p & ~127) + ((p & 31) << 2) + ((p >> 5) & 3);
        shS[p] = sv[lg];
        shC[p] = cv[lg];
    }
    __syncthreads();

    const int ib = i0 + warp * 2;                       // first of 2 rows
    const uint32_t* Wb = g_W + ((size_t)b * HH + ib) * HH;

    u64 acc[2][4];                                       // [row][s1d01,s1d23,s2d01,s2d23]
    #pragma unroll
    for (int r = 0; r < 2; r++)
        #pragma unroll
        for (int q = 0; q < 4; q++) acc[r][q] = 0;

    // prefetch jq=0 (lane covers j = jq*128 + lane*4 .. +3)
    uint4 nw[2];
    #pragma unroll
    for (int r = 0; r < 2; r++)
        nw[r] = *(const uint4*)(Wb + r * HH + lane * 4);

    for (int jq = 0; jq < 8; jq++) {
        uint4 w[2];
        w[0] = nw[0]; w[1] = nw[1];
        if (jq < 7) {
            const int jb2 = (jq + 1) * 128 + lane * 4;
            nw[0] = *(const uint4*)(Wb + 0 * HH + jb2);
            nw[1] = *(const uint4*)(Wb + 1 * HH + jb2);
        }

        #pragma unroll
        for (int k = 0; k < 4; k++) {
            // permuted, conflict-free: consecutive lanes -> consecutive 16B
            ulonglong2 Sv = shS[jq * 128 + k * 32 + lane];
            ulonglong2 Cv = shC[jq * 128 + k * 32 + lane];
            #pragma unroll
            for (int r = 0; r < 2; r++) {
                uint32_t u = (k == 0) ? w[r].x : (k == 1) ? w[r].y
                           : (k == 2) ? w[r].z : w[r].w;
                float w1f = __uint_as_float(u << 16);
                float w2f = __uint_as_float(u & 0xFFFF0000u);
                u64 w1p = pack2(w1f, w1f);
                u64 w2p = pack2(w2f, w2f);
                u64 n2p = pack2(-w2f, -w2f);
                acc[r][0] = ffma2(w1p, Sv.x, acc[r][0]);
                acc[r][0] = ffma2(n2p, Cv.x, acc[r][0]);
                acc[r][1] = ffma2(w1p, Sv.y, acc[r][1]);
                acc[r][1] = ffma2(n2p, Cv.y, acc[r][1]);
                acc[r][2] = ffma2(w1p, Cv.x, acc[r][2]);
                acc[r][2] = ffma2(w2p, Sv.x, acc[r][2]);
                acc[r][3] = ffma2(w1p, Cv.y, acc[r][3]);
                acc[r][3] = ffma2(w2p, Sv.y, acc[r][3]);
            }
        }
    }

    // unpack 8 u64 -> 16 floats, butterfly-reduce across the warp
    float v[16];
    #pragma unroll
    for (int r = 0; r < 2; r++) {
        float2 t2;
        t2 = unpk2(acc[r][0]); v[r * 8 + 0] = t2.x; v[r * 8 + 1] = t2.y;  // s1 d0,d1
        t2 = unpk2(acc[r][1]); v[r * 8 + 2] = t2.x; v[r * 8 + 3] = t2.y;  // s1 d2,d3
        t2 = unpk2(acc[r][2]); v[r * 8 + 4] = t2.x; v[r * 8 + 5] = t2.y;  // s2 d0,d1
        t2 = unpk2(acc[r][3]); v[r * 8 + 6] = t2.x; v[r * 8 + 7] = t2.y;  // s2 d2,d3
    }
    #pragma unroll
    for (int off = 16; off > 0; off >>= 1) {
        #pragma unroll
        for (int q = 0; q < 16; q++)
            v[q] += __shfl_xor_sync(0xFFFFFFFFu, v[q], off);
    }

    if (lane < 2) {
        const int i = ib + lane;
        const float* vv = v + lane * 8;       // [s1_d0..d3, s2_d0..d3]
        const float invH = 1.0f / (float)HH;  // K_COUP=1, DT=1, 0.5 folded
        const size_t base = ((size_t)b * HH + i) * DD;
        float4 si4 = *(const float4*)(g_sth + base);
        float4 ci4 = *(const float4*)(g_cth + base);
        float4 tp4 = *(const float4*)(theta + base);
        float4 om4 = *(const float4*)(omega + (size_t)i * DD);
        float4 kp4 = *(const float4*)(kappa + (size_t)i * DD);
        float g = gamma[(size_t)b * HH + i];

        float4 rr;
        rr.x = tp4.x + om4.x + invH * (ci4.x * vv[0] - si4.x * vv[4]) + kp4.x * (g - tp4.x);
        rr.y = tp4.y + om4.y + invH * (ci4.y * vv[1] - si4.y * vv[5]) + kp4.y * (g - tp4.y);
        rr.z = tp4.z + om4.z + invH * (ci4.z * vv[2] - si4.z * vv[6]) + kp4.z * (g - tp4.z);
        rr.w = tp4.w + om4.w + invH * (ci4.w * vv[3] - si4.w * vv[7]) + kp4.w * (g - tp4.w);
        *(float4*)(out + base) = rr;
    }
}

extern "C" void kernel_launch(void* const* d_in, const int* in_sizes, int n_in,
                              void* d_out, int out_size) {
    const float* theta = (const float*)d_in[0];  // [B,H,D]
    const float* gamma = (const float*)d_in[1];  // [B,H]
    const float* A     = (const float*)d_in[2];  // [B,H,H]
    const float* omega = (const float*)d_in[3];  // [H,D]
    const float* kappa = (const float*)d_in[4];  // [H,D]
    const float* alpha = (const float*)d_in[5];  // [H,H]
    float* out = (float*)d_out;

    vk_symw_kernel<<<NPAIR, 256>>>(A, alpha, theta);
    {
        dim3 grid(HH / 16, BB);
        vk_main_kernel<<<grid, 256>>>(theta, gamma, omega, kappa, out);
    }
}